// round 5
// baseline (speedup 1.0000x reference)
#include <cuda_runtime.h>

#define T_STEPS 512
#define BATCH   2048
#define IN_DIM  28
#define HID     198
#define OUT_DIM 10

#define BBLK     16
#define NBLOCKS  (BATCH / BBLK)   // 128
#define NTHREADS 256

#define KPAD 200                  // k padded to 200 (50 exact float4 quads), pad = 0
#define HSTR 204                  // H_s / h_s row stride in floats (204 mod 32 = 12 -> conflict-free LDS.128)
#define USTR 36                   // U_s row stride (36 mod 32 = 4 -> conflict-free LDS.128)
#define XSTR 32                   // x_s row stride

// shared memory layout (in floats)
#define H_S_OFF   0
#define U_S_OFF   (HID * HSTR)                 // 40392
#define HST_S_OFF (U_S_OFF + HID * USTR)       // + 7128  = 47520 (hidden state)
#define X_S_OFF   (HST_S_OFF + BBLK * HSTR)    // + 3264  = 50784
#define B_S_OFF   (X_S_OFF + BBLK * XSTR)      // + 512   = 51296
#define SMEM_FLOATS (B_S_OFF + KPAD)           // 51496 -> 205984 bytes

// Per-step fused GEMM:  acc[r][m] = b[j] + sum_k x[bb][k]*U[k][j] + sum_k h[bb][k]*H[j][k]
// Thread tile: 4 batch rows (r) x NJ j-columns (m), j = jl + 64*m (clamped; invalid slots
// compute garbage into unstored accumulators).
template<int NJ>
__device__ __forceinline__ void step_gemm(
    float (&acc)[4][4],
    const float* __restrict__ sm_H, const float* __restrict__ sm_U,
    const float* __restrict__ sm_h, const float* __restrict__ sm_x,
    const float* __restrict__ sm_b,
    int bb0, int jl)
{
    int jj[NJ];
#pragma unroll
    for (int m = 0; m < NJ; m++) {
        int j = jl + 64 * m;
        jj[m] = (j < HID) ? j : 0;          // clamp keeps smem reads in-bounds
    }

#pragma unroll
    for (int r = 0; r < 4; r++)
#pragma unroll
        for (int m = 0; m < NJ; m++)
            acc[r][m] = sm_b[jj[m]];

    // input projection part: K = 28 -> 7 exact quads
#pragma unroll
    for (int kq = 0; kq < IN_DIM / 4; kq++) {
        float4 xv[4];
#pragma unroll
        for (int r = 0; r < 4; r++)
            xv[r] = *reinterpret_cast<const float4*>(sm_x + (bb0 + r) * XSTR + kq * 4);
#pragma unroll
        for (int m = 0; m < NJ; m++) {
            float4 uv = *reinterpret_cast<const float4*>(sm_U + jj[m] * USTR + kq * 4);
#pragma unroll
            for (int r = 0; r < 4; r++) {
                acc[r][m] += xv[r].x * uv.x;
                acc[r][m] += xv[r].y * uv.y;
                acc[r][m] += xv[r].z * uv.z;
                acc[r][m] += xv[r].w * uv.w;
            }
        }
    }

    // recurrent part: K padded to 200 -> 50 exact quads (pad columns are zero)
#pragma unroll 5
    for (int kq = 0; kq < KPAD / 4; kq++) {
        float4 hv[4];
#pragma unroll
        for (int r = 0; r < 4; r++)
            hv[r] = *reinterpret_cast<const float4*>(sm_h + (bb0 + r) * HSTR + kq * 4);
#pragma unroll
        for (int m = 0; m < NJ; m++) {
            float4 wv = *reinterpret_cast<const float4*>(sm_H + jj[m] * HSTR + kq * 4);
#pragma unroll
            for (int r = 0; r < 4; r++) {
                acc[r][m] += hv[r].x * wv.x;
                acc[r][m] += hv[r].y * wv.y;
                acc[r][m] += hv[r].z * wv.z;
                acc[r][m] += hv[r].w * wv.w;
            }
        }
    }
}

__global__ __launch_bounds__(NTHREADS, 1)
void SimpleRNN_kernel(const float* __restrict__ x, const float* __restrict__ H,
                      const float* __restrict__ U, const float* __restrict__ A,
                      const float* __restrict__ bvec, const float* __restrict__ cvec,
                      float* __restrict__ out)
{
    extern __shared__ float sm[];
    float* sm_H = sm + H_S_OFF;
    float* sm_U = sm + U_S_OFF;
    float* sm_h = sm + HST_S_OFF;
    float* sm_x = sm + X_S_OFF;
    float* sm_b = sm + B_S_OFF;

    const int tid = threadIdx.x;
    const int b0  = blockIdx.x * BBLK;

    // ---- one-time weight staging ----
    for (int i = tid; i < HID * HSTR; i += NTHREADS) {
        int j = i / HSTR, k = i - j * HSTR;
        sm_H[i] = (k < HID) ? H[j * HID + k] : 0.f;       // H[j][k], k-padded with zeros
    }
    for (int i = tid; i < HID * USTR; i += NTHREADS) {
        int j = i / USTR, k = i - j * USTR;
        sm_U[i] = (k < IN_DIM) ? U[k * HID + j] : 0.f;    // transposed: U_s[j][k]
    }
    for (int i = tid; i < KPAD; i += NTHREADS)
        sm_b[i] = (i < HID) ? bvec[i] : 0.f;
    for (int i = tid; i < BBLK * HSTR; i += NTHREADS)
        sm_h[i] = 0.f;                                     // h0 = 0 (pad cols stay 0 forever)
    __syncthreads();

    const int  jl   = tid & 63;          // j lane 0..63
    const int  bb0  = (tid >> 6) * 4;    // batch-row group base 0,4,8,12
    const bool has4 = (jl < 32);         // warp-uniform: first warp of each group carries j-tail

    for (int t = 0; t < T_STEPS; t++) {
        // stage x[t, b0:b0+16, :] (contiguous 448 floats)
        const float* gx = x + (size_t)t * (BATCH * IN_DIM) + (size_t)b0 * IN_DIM;
        for (int i = tid; i < BBLK * IN_DIM; i += NTHREADS) {
            int bb = i / IN_DIM;
            int k  = i - bb * IN_DIM;
            sm_x[bb * XSTR + k] = gx[i];
        }
        __syncthreads();   // x_s ready; previous h_s writes visible

        float acc[4][4];
        if (has4) step_gemm<4>(acc, sm_H, sm_U, sm_h, sm_x, sm_b, bb0, jl);
        else      step_gemm<3>(acc, sm_H, sm_U, sm_h, sm_x, sm_b, bb0, jl);

        __syncthreads();   // all reads of h_s done before overwrite

#pragma unroll
        for (int r = 0; r < 4; r++) {
            float* hrow = sm_h + (bb0 + r) * HSTR;
#pragma unroll
            for (int m = 0; m < 3; m++)
                hrow[jl + 64 * m] = tanhf(acc[r][m]);
        }
        if (jl + 192 < HID) {            // only lanes 0..5 of has4 warps
#pragma unroll
            for (int r = 0; r < 4; r++)
                sm_h[(bb0 + r) * HSTR + jl + 192] = tanhf(acc[r][3]);
        }
    }
    __syncthreads();

    // ---- output projection: out[b][o] = h[b] . A[o] + c[o]  (16 x 10 per block) ----
    if (tid < BBLK * OUT_DIM) {
        int bb = tid / OUT_DIM;
        int o  = tid - bb * OUT_DIM;
        float s = cvec[o];
        const float* hrow = sm_h + bb * HSTR;
        const float* arow = A + o * HID;
#pragma unroll 4
        for (int j = 0; j < HID; j++)
            s += hrow[j] * arow[j];
        out[(b0 + bb) * OUT_DIM + o] = s;
    }
}

extern "C" void kernel_launch(void* const* d_in, const int* in_sizes, int n_in,
                              void* d_out, int out_size)
{
    // identify inputs by element count (all distinct): robust to ordering
    const float *x = nullptr, *H = nullptr, *U = nullptr, *A = nullptr, *b = nullptr, *c = nullptr;
    for (int i = 0; i < n_in; i++) {
        const float* p = (const float*)d_in[i];
        switch (in_sizes[i]) {
            case T_STEPS * BATCH * IN_DIM: x = p; break;   // 29,360,128
            case HID * HID:                H = p; break;   // 39,204
            case IN_DIM * HID:             U = p; break;   // 5,544
            case OUT_DIM * HID:            A = p; break;   // 1,980
            case HID:                      b = p; break;   // 198
            case OUT_DIM:                  c = p; break;   // 10
            default: break;
        }
    }
    float* out = (float*)d_out;

    size_t smem_bytes = SMEM_FLOATS * sizeof(float);   // 205,984 B (< 227 KB limit)
    cudaFuncSetAttribute(SimpleRNN_kernel,
                         cudaFuncAttributeMaxDynamicSharedMemorySize, (int)smem_bytes);

    SimpleRNN_kernel<<<NBLOCKS, NTHREADS, smem_bytes>>>(x, H, U, A, b, c, out);
}